// round 2
// baseline (speedup 1.0000x reference)
#include <cuda_runtime.h>
#include <cuda_bf16.h>
#include <cstdint>

// ---------------- problem constants ----------------
static constexpr int NN  = 40000;     // nodes
static constexpr int NE  = 1280000;   // edges
static constexpr int DF  = 1024;      // input feat
static constexpr int HID = 64;        // hidden
static constexpr int NC  = 40;        // classes

// ---------------- device scratch ----------------
__device__ float g_H1[(size_t)NN * HID];   // x @ W1
__device__ float g_O1[(size_t)NN * HID];   // aggregated layer-1
__device__ float g_H2[(size_t)NN * NC];    // relu(O1+b1) @ W2
__device__ float g_O2[(size_t)NN * NC];    // aggregated layer-2
__device__ float g_dinv[NN];
__device__ unsigned int g_deg[NN];
__device__ __nv_bfloat16 g_W1h[(size_t)HID * DF];  // W1^T hi, [n][k]
__device__ __nv_bfloat16 g_W1l[(size_t)HID * DF];  // W1^T lo, [n][k]

// ---------------- helpers ----------------
__device__ __forceinline__ uint32_t smem_to_u32(const void* p) {
    uint32_t a;
    asm("{ .reg .u64 t; cvta.to.shared.u64 t, %1; cvt.u32.u64 %0, t; }" : "=r"(a) : "l"(p));
    return a;
}
__device__ __forceinline__ uint32_t bfbits(__nv_bfloat16 h) {
    return (uint32_t)__bfloat16_as_ushort(h);
}
// vectorized float4 global reduction (sm_90+)
__device__ __forceinline__ void red_add_v4(float* addr, float a, float b, float c, float d) {
    asm volatile("red.global.add.v4.f32 [%0], {%1, %2, %3, %4};"
                 :: "l"(addr), "f"(a), "f"(b), "f"(c), "f"(d) : "memory");
}
#define LDSM4(r, addr) \
    asm volatile("ldmatrix.sync.aligned.m8n8.x4.shared.b16 {%0,%1,%2,%3}, [%4];" \
                 : "=r"((r)[0]), "=r"((r)[1]), "=r"((r)[2]), "=r"((r)[3]) : "r"(addr))
__device__ __forceinline__ void mma16816(float* c, const uint32_t* a, uint32_t b0, uint32_t b1) {
    asm volatile(
        "mma.sync.aligned.m16n8k16.row.col.f32.bf16.bf16.f32 "
        "{%0,%1,%2,%3}, {%4,%5,%6,%7}, {%8,%9}, {%0,%1,%2,%3};"
        : "+f"(c[0]), "+f"(c[1]), "+f"(c[2]), "+f"(c[3])
        : "r"(a[0]), "r"(a[1]), "r"(a[2]), "r"(a[3]), "r"(b0), "r"(b1));
}

// ---------------- small prep kernels ----------------
__global__ void k_deg_init() {
    int i = blockIdx.x * blockDim.x + threadIdx.x;
    if (i < NN) g_deg[i] = 1u;  // self-loop
}
__global__ void k_deg_count(const int* __restrict__ col) {
    int e = blockIdx.x * blockDim.x + threadIdx.x;
    if (e < NE) atomicAdd(&g_deg[col[e]], 1u);
}
__global__ void k_dinv() {
    int i = blockIdx.x * blockDim.x + threadIdx.x;
    if (i < NN) g_dinv[i] = rsqrtf((float)g_deg[i]);
}
// split W1 [DF][HID] into bf16 hi/lo, transposed to [HID][DF]
__global__ void k_wsplit(const float* __restrict__ W1) {
    int idx = blockIdx.x * blockDim.x + threadIdx.x;
    if (idx >= DF * HID) return;
    int k = idx >> 6, n = idx & 63;
    float w = W1[idx];
    __nv_bfloat16 hi = __float2bfloat16(w);
    float lo = w - __bfloat162float(hi);
    g_W1h[(size_t)n * DF + k] = hi;
    g_W1l[(size_t)n * DF + k] = __float2bfloat16(lo);
}

// ---------------- GEMM1: mma.sync bf16 hi/lo compensated ----------------
// Block: 256 thr / 8 warps. Tile M=128, N=64, K-chunks of 64.
// Warp w computes rows [w*16, w*16+16) x all 64 cols.
// smem: A stride 72 bf16 (144B rows, conflict-free ldmatrix).
static constexpr int SA_STRIDE = 72;                     // bf16 elems per row
static constexpr int SAH_OFF = 0;
static constexpr int SAL_OFF = 128 * SA_STRIDE * 2;      // 18432
static constexpr int SBH_OFF = SAL_OFF * 2;              // 36864
static constexpr int SBL_OFF = SBH_OFF + 64 * SA_STRIDE * 2;  // 46080
static constexpr int SM_TOTAL = SBL_OFF + 64 * SA_STRIDE * 2; // 55296

__global__ void __launch_bounds__(256) k_gemm1(const float* __restrict__ x) {
    extern __shared__ char sm[];
    const uint32_t smb = smem_to_u32(sm);
    const int t = threadIdx.x;
    const int lane = t & 31, w = t >> 5;
    const int m0 = blockIdx.x * 128;

    // ---- A cooperative-load mapping: thread -> (row, half of 64 cols) ----
    const int arow = t >> 1, ahalf = t & 1;
    const bool avalid = (m0 + arow) < NN;
    const float4* xrow = (const float4*)(x + (size_t)(m0 + arow) * DF);
    const uint32_t aDstByte = (uint32_t)(arow * (SA_STRIDE * 2) + ahalf * 64);

    // ---- ldmatrix per-lane addresses ----
    // A tile for warp w, 16x16 k-step: lanes 0-7 rows 0-7, 8-15 rows 8-15 (k0-7),
    // 16-23 rows 0-7 (k8-15), 24-31 rows 8-15 (k8-15)
    const uint32_t aLd = smb +
        (uint32_t)((w * 16 + (lane & 7) + ((lane >> 3) & 1) * 8) * (SA_STRIDE * 2) +
                   (lane >> 4) * 16);
    // B: x4 covers ntile pair: m0=ntile j k0-7, m1=ntile j k8-15, m2=ntile j+1 k0-7, m3=...
    const uint32_t bLd = smb +
        (uint32_t)((((lane >> 4) * 8) + (lane & 7)) * (SA_STRIDE * 2) +
                   ((lane >> 3) & 1) * 16);

    float acc[8][4];
#pragma unroll
    for (int j = 0; j < 8; j++)
#pragma unroll
        for (int q = 0; q < 4; q++) acc[j][q] = 0.f;

    for (int kc = 0; kc < 16; kc++) {
        // ---- load & convert A: 128x64 f32 -> bf16 hi/lo ----
#pragma unroll
        for (int i = 0; i < 8; i++) {
            float4 v = avalid ? __ldg(xrow + kc * 16 + ahalf * 8 + i)
                              : make_float4(0.f, 0.f, 0.f, 0.f);
            __nv_bfloat16 hx = __float2bfloat16(v.x), hy = __float2bfloat16(v.y);
            __nv_bfloat16 hz = __float2bfloat16(v.z), hw = __float2bfloat16(v.w);
            *(uint2*)(sm + SAH_OFF + aDstByte + i * 8) =
                make_uint2(bfbits(hx) | (bfbits(hy) << 16), bfbits(hz) | (bfbits(hw) << 16));
            __nv_bfloat16 lx = __float2bfloat16(v.x - __bfloat162float(hx));
            __nv_bfloat16 ly = __float2bfloat16(v.y - __bfloat162float(hy));
            __nv_bfloat16 lz = __float2bfloat16(v.z - __bfloat162float(hz));
            __nv_bfloat16 lw = __float2bfloat16(v.w - __bfloat162float(hw));
            *(uint2*)(sm + SAL_OFF + aDstByte + i * 8) =
                make_uint2(bfbits(lx) | (bfbits(ly) << 16), bfbits(lz) | (bfbits(lw) << 16));
        }
        // ---- load B chunk: W1^T hi/lo [64 n][64 k] bf16 ----
#pragma unroll
        for (int j = 0; j < 4; j++) {
            int lin = t + j * 256;
            int n = lin >> 4, q = lin & 15;
            size_t src = (size_t)n * DF + kc * 64 + q * 4;
            uint32_t dst = (uint32_t)(n * (SA_STRIDE * 2) + q * 8);
            *(uint2*)(sm + SBH_OFF + dst) = __ldg((const uint2*)(g_W1h + src));
            *(uint2*)(sm + SBL_OFF + dst) = __ldg((const uint2*)(g_W1l + src));
        }
        __syncthreads();

        // ---- compute: 4 k16 steps x 8 ntiles x 3 passes ----
#pragma unroll
        for (int ks = 0; ks < 4; ks++) {
            uint32_t ah[4], al[4];
            LDSM4(ah, aLd + SAH_OFF + ks * 32);
            LDSM4(al, aLd + SAL_OFF + ks * 32);
#pragma unroll
            for (int jp = 0; jp < 4; jp++) {
                uint32_t bh[4], bl[4];
                LDSM4(bh, bLd + SBH_OFF + jp * (16 * SA_STRIDE * 2) + ks * 32);
                LDSM4(bl, bLd + SBL_OFF + jp * (16 * SA_STRIDE * 2) + ks * 32);
                mma16816(acc[2 * jp],     ah, bh[0], bh[1]);
                mma16816(acc[2 * jp],     ah, bl[0], bl[1]);
                mma16816(acc[2 * jp],     al, bh[0], bh[1]);
                mma16816(acc[2 * jp + 1], ah, bh[2], bh[3]);
                mma16816(acc[2 * jp + 1], ah, bl[2], bl[3]);
                mma16816(acc[2 * jp + 1], al, bh[2], bh[3]);
            }
        }
        __syncthreads();
    }

    // ---- epilogue ----
    const int g = lane >> 2, tig = lane & 3;
    const int r0 = m0 + w * 16 + g;
    const int r1 = r0 + 8;
#pragma unroll
    for (int nt = 0; nt < 8; nt++) {
        int c = nt * 8 + tig * 2;
        if (r0 < NN) *(float2*)(g_H1 + (size_t)r0 * 64 + c) = make_float2(acc[nt][0], acc[nt][1]);
        if (r1 < NN) *(float2*)(g_H1 + (size_t)r1 * 64 + c) = make_float2(acc[nt][2], acc[nt][3]);
    }
}

// ---------------- scatter layer 1 ----------------
__global__ void k_o1_init() {  // self loop: O1[i] = H1[i] * dinv[i]^2
    int i = blockIdx.x * blockDim.x + threadIdx.x;  // float4 index, NN*16 total
    if (i >= NN * 16) return;
    int n = i >> 4;
    float s = g_dinv[n]; s *= s;
    float4 v = ((const float4*)g_H1)[i];
    ((float4*)g_O1)[i] = make_float4(v.x * s, v.y * s, v.z * s, v.w * s);
}
__global__ void k_scatter1(const int* __restrict__ row, const int* __restrict__ col) {
    int t = blockIdx.x * blockDim.x + threadIdx.x;  // NE*8 threads
    if (t >= NE * 8) return;
    int e = t >> 3, j = t & 7;
    int r = __ldg(row + e), c = __ldg(col + e);
    float w = __ldg(g_dinv + r) * __ldg(g_dinv + c);
    const float4* src = (const float4*)(g_H1 + (size_t)r * 64) + j * 2;
    float* dst = g_O1 + (size_t)c * 64 + j * 8;
    float4 v0 = __ldg(src), v1 = __ldg(src + 1);
    red_add_v4(dst,     v0.x * w, v0.y * w, v0.z * w, v0.w * w);
    red_add_v4(dst + 4, v1.x * w, v1.y * w, v1.z * w, v1.w * w);
}

// ---------------- GEMM2: relu(O1 + b1) @ W2 ----------------
__global__ void __launch_bounds__(256) k_gemm2(const float* __restrict__ b1,
                                               const float* __restrict__ W2) {
    __shared__ float sW[HID * NC];
    __shared__ float sb[HID];
    for (int i = threadIdx.x; i < HID * NC; i += blockDim.x) sW[i] = W2[i];
    if (threadIdx.x < HID) sb[threadIdx.x] = b1[threadIdx.x];
    __syncthreads();
    int r = blockIdx.x * blockDim.x + threadIdx.x;
    if (r >= NN) return;
    float acc[NC];
#pragma unroll
    for (int n = 0; n < NC; n++) acc[n] = 0.f;
    const float* a = g_O1 + (size_t)r * HID;
#pragma unroll 4
    for (int k = 0; k < HID; k++) {
        float av = fmaxf(a[k] + sb[k], 0.f);
#pragma unroll
        for (int n = 0; n < NC; n++) acc[n] = fmaf(av, sW[k * NC + n], acc[n]);
    }
    float* o = g_H2 + (size_t)r * NC;
#pragma unroll
    for (int n = 0; n < NC; n++) o[n] = acc[n];
}

// ---------------- scatter layer 2 ----------------
__global__ void k_o2_init() {
    int i = blockIdx.x * blockDim.x + threadIdx.x;  // float4 index, NN*10 total
    if (i >= NN * 10) return;
    int n = i / 10;
    float s = g_dinv[n]; s *= s;
    float4 v = ((const float4*)g_H2)[i];
    ((float4*)g_O2)[i] = make_float4(v.x * s, v.y * s, v.z * s, v.w * s);
}
__global__ void k_scatter2(const int* __restrict__ row, const int* __restrict__ col) {
    int t = blockIdx.x * blockDim.x + threadIdx.x;  // NE*10 threads
    if (t >= NE * 10) return;
    int e = t / 10, j = t - e * 10;
    int r = __ldg(row + e), c = __ldg(col + e);
    float w = __ldg(g_dinv + r) * __ldg(g_dinv + c);
    float4 v = __ldg((const float4*)(g_H2 + (size_t)r * NC) + j);
    red_add_v4(g_O2 + (size_t)c * NC + j * 4, v.x * w, v.y * w, v.z * w, v.w * w);
}

// ---------------- log_softmax(O2 + b2) ----------------
__global__ void k_lsm(const float* __restrict__ b2, float* __restrict__ out) {
    int r = blockIdx.x * blockDim.x + threadIdx.x;
    if (r >= NN) return;
    const float* z0 = g_O2 + (size_t)r * NC;
    float z[NC];
    float m = -1e30f;
#pragma unroll
    for (int c = 0; c < NC; c++) { z[c] = z0[c] + b2[c]; m = fmaxf(m, z[c]); }
    float s = 0.f;
#pragma unroll
    for (int c = 0; c < NC; c++) s += expf(z[c] - m);
    float l = m + logf(s);
    float* o = out + (size_t)r * NC;
#pragma unroll
    for (int c = 0; c < NC; c++) o[c] = z[c] - l;
}

// ---------------- launch ----------------
extern "C" void kernel_launch(void* const* d_in, const int* in_sizes, int n_in,
                              void* d_out, int out_size) {
    const float* x  = (const float*)d_in[0];
    const int*   ei = (const int*)d_in[1];
    const float* W1 = (const float*)d_in[2];
    const float* b1 = (const float*)d_in[3];
    const float* W2 = (const float*)d_in[4];
    const float* b2 = (const float*)d_in[5];
    const int* row = ei;         // sources
    const int* col = ei + NE;    // targets
    float* out = (float*)d_out;

    static bool attr_set = false;
    if (!attr_set) {
        cudaFuncSetAttribute(k_gemm1, cudaFuncAttributeMaxDynamicSharedMemorySize, SM_TOTAL);
        attr_set = true;
    }

    k_deg_init<<<(NN + 255) / 256, 256>>>();
    k_deg_count<<<(NE + 255) / 256, 256>>>(col);
    k_dinv<<<(NN + 255) / 256, 256>>>();
    k_wsplit<<<(DF * HID + 255) / 256, 256>>>(W1);

    k_gemm1<<<(NN + 127) / 128, 256, SM_TOTAL>>>(x);

    k_o1_init<<<(NN * 16 + 255) / 256, 256>>>();
    k_scatter1<<<(NE * 8 + 255) / 256, 256>>>(row, col);

    k_gemm2<<<(NN + 255) / 256, 256>>>(b1, W2);

    k_o2_init<<<(NN * 10 + 255) / 256, 256>>>();
    k_scatter2<<<(NE * 10 + 255) / 256, 256>>>(row, col);

    k_lsm<<<(NN + 255) / 256, 256>>>(b2, out);
}

// round 3
// speedup vs baseline: 1.3028x; 1.3028x over previous
#include <cuda_runtime.h>
#include <cuda_bf16.h>
#include <cstdint>
#include <math_constants.h>

// ---------------- problem constants ----------------
static constexpr int NN  = 40000;     // nodes
static constexpr int NE  = 1280000;   // edges
static constexpr int DF  = 1024;      // input feat
static constexpr int HID = 64;        // hidden
static constexpr int NC  = 40;        // classes

// ---------------- device scratch ----------------
__device__ float g_H1[(size_t)NN * HID];   // x @ W1
__device__ float g_O1[(size_t)NN * HID];   // relu(A_hat @ H1 + b1)
__device__ float g_H2[(size_t)NN * NC];    // O1 @ W2
__device__ float g_dinv[NN];
__device__ int   g_deg[NN];                // in-degree (no self loop)
__device__ int   g_rowptr[NN];             // CSR start per node
__device__ int   g_cursor[NN];
__device__ int   g_rowtmp[NN];             // inclusive scan, pre-base
__device__ int   g_bsum[160];
__device__ int   g_bbase[160];
__device__ int2  g_edge[NE];               // (src, weight-bits) sorted by dst
__device__ __nv_bfloat16 g_W1h[(size_t)HID * DF];  // W1^T hi, [n][k]
__device__ __nv_bfloat16 g_W1l[(size_t)HID * DF];  // W1^T lo, [n][k]

// ---------------- helpers ----------------
__device__ __forceinline__ uint32_t smem_to_u32(const void* p) {
    uint32_t a;
    asm("{ .reg .u64 t; cvta.to.shared.u64 t, %1; cvt.u32.u64 %0, t; }" : "=r"(a) : "l"(p));
    return a;
}
__device__ __forceinline__ uint32_t bfbits(__nv_bfloat16 h) {
    return (uint32_t)__bfloat16_as_ushort(h);
}
#define LDSM4(r, addr) \
    asm volatile("ldmatrix.sync.aligned.m8n8.x4.shared.b16 {%0,%1,%2,%3}, [%4];" \
                 : "=r"((r)[0]), "=r"((r)[1]), "=r"((r)[2]), "=r"((r)[3]) : "r"(addr))
__device__ __forceinline__ void mma16816(float* c, const uint32_t* a, uint32_t b0, uint32_t b1) {
    asm volatile(
        "mma.sync.aligned.m16n8k16.row.col.f32.bf16.bf16.f32 "
        "{%0,%1,%2,%3}, {%4,%5,%6,%7}, {%8,%9}, {%0,%1,%2,%3};"
        : "+f"(c[0]), "+f"(c[1]), "+f"(c[2]), "+f"(c[3])
        : "r"(a[0]), "r"(a[1]), "r"(a[2]), "r"(a[3]), "r"(b0), "r"(b1));
}

// ---------------- prep: degree, dinv, W split ----------------
__global__ void k_deg_init() {
    int i = blockIdx.x * blockDim.x + threadIdx.x;
    if (i < NN) g_deg[i] = 0;
}
__global__ void k_hist(const int* __restrict__ col) {
    int e = blockIdx.x * blockDim.x + threadIdx.x;
    if (e < NE) atomicAdd(&g_deg[col[e]], 1);
}
__global__ void k_dinv() {
    int i = blockIdx.x * blockDim.x + threadIdx.x;
    if (i < NN) g_dinv[i] = rsqrtf((float)(g_deg[i] + 1));  // +1 self loop
}
__global__ void k_wsplit(const float* __restrict__ W1) {
    int idx = blockIdx.x * blockDim.x + threadIdx.x;
    if (idx >= DF * HID) return;
    int k = idx >> 6, n = idx & 63;
    float w = W1[idx];
    __nv_bfloat16 hi = __float2bfloat16(w);
    float lo = w - __bfloat162float(hi);
    g_W1h[(size_t)n * DF + k] = hi;
    g_W1l[(size_t)n * DF + k] = __float2bfloat16(lo);
}

// ---------------- CSR build: 3-phase scan + fill ----------------
static constexpr int SCAN_NB = (NN + 255) / 256;  // 157
__global__ void k_scanA() {
    __shared__ int s[256];
    int i = blockIdx.x * 256 + threadIdx.x;
    int v = (i < NN) ? g_deg[i] : 0;
    s[threadIdx.x] = v;
    __syncthreads();
#pragma unroll
    for (int off = 1; off < 256; off <<= 1) {
        int t = (threadIdx.x >= off) ? s[threadIdx.x - off] : 0;
        __syncthreads();
        s[threadIdx.x] += t;
        __syncthreads();
    }
    if (i < NN) g_rowtmp[i] = s[threadIdx.x];
    if (threadIdx.x == 255) g_bsum[blockIdx.x] = s[255];
}
__global__ void k_scanB() {
    __shared__ int s[256];
    int v = (threadIdx.x < SCAN_NB) ? g_bsum[threadIdx.x] : 0;
    s[threadIdx.x] = v;
    __syncthreads();
#pragma unroll
    for (int off = 1; off < 256; off <<= 1) {
        int t = (threadIdx.x >= off) ? s[threadIdx.x - off] : 0;
        __syncthreads();
        s[threadIdx.x] += t;
        __syncthreads();
    }
    if (threadIdx.x < SCAN_NB) g_bbase[threadIdx.x] = s[threadIdx.x] - v;  // exclusive
}
__global__ void k_scanC() {
    int i = blockIdx.x * 256 + threadIdx.x;
    if (i >= NN) return;
    int start = g_rowtmp[i] + g_bbase[blockIdx.x] - g_deg[i];
    g_rowptr[i] = start;
    g_cursor[i] = start;
}
__global__ void k_fill(const int* __restrict__ row, const int* __restrict__ col) {
    int e = blockIdx.x * blockDim.x + threadIdx.x;
    if (e >= NE) return;
    int r = __ldg(row + e), c = __ldg(col + e);
    int p = atomicAdd(&g_cursor[c], 1);
    float w = __ldg(g_dinv + r) * __ldg(g_dinv + c);
    g_edge[p] = make_int2(r, __float_as_int(w));
}

// ---------------- GEMM1: mma.sync bf16 hi/lo compensated, A-prefetch pipelined ----------------
static constexpr int SA_STRIDE = 72;                     // bf16 elems per row
static constexpr int SAH_OFF = 0;
static constexpr int SAL_OFF = 128 * SA_STRIDE * 2;      // 18432
static constexpr int SBH_OFF = SAL_OFF * 2;              // 36864
static constexpr int SBL_OFF = SBH_OFF + 64 * SA_STRIDE * 2;  // 46080
static constexpr int SM_TOTAL = SBL_OFF + 64 * SA_STRIDE * 2; // 55296

__global__ void __launch_bounds__(256, 2) k_gemm1(const float* __restrict__ x) {
    extern __shared__ char sm[];
    const uint32_t smb = smem_to_u32(sm);
    const int t = threadIdx.x;
    const int lane = t & 31, w = t >> 5;
    const int m0 = blockIdx.x * 128;

    const int arow = t >> 1, ahalf = t & 1;
    const bool avalid = (m0 + arow) < NN;
    const float4* xrow = (const float4*)(x + (size_t)(m0 + arow) * DF);
    const uint32_t aDstByte = (uint32_t)(arow * (SA_STRIDE * 2) + ahalf * 64);

    const uint32_t aLd = smb +
        (uint32_t)((w * 16 + (lane & 7) + ((lane >> 3) & 1) * 8) * (SA_STRIDE * 2) +
                   (lane >> 4) * 16);
    const uint32_t bLd = smb +
        (uint32_t)((((lane >> 4) * 8) + (lane & 7)) * (SA_STRIDE * 2) +
                   ((lane >> 3) & 1) * 16);

    float acc[8][4];
#pragma unroll
    for (int j = 0; j < 8; j++)
#pragma unroll
        for (int q = 0; q < 4; q++) acc[j][q] = 0.f;

    float4 pf[8];
#pragma unroll
    for (int i = 0; i < 8; i++)
        pf[i] = avalid ? __ldg(xrow + ahalf * 8 + i) : make_float4(0.f, 0.f, 0.f, 0.f);

    for (int kc = 0; kc < 16; kc++) {
        // ---- B global loads first (latency overlaps A convert ALU) ----
        uint2 bh[4], bl[4];
#pragma unroll
        for (int j = 0; j < 4; j++) {
            int lin = t + j * 256;
            int n = lin >> 4, q = lin & 15;
            size_t src = (size_t)n * DF + kc * 64 + q * 4;
            bh[j] = __ldg((const uint2*)(g_W1h + src));
            bl[j] = __ldg((const uint2*)(g_W1l + src));
        }
        // ---- convert prefetched A: f32 -> bf16 hi/lo ----
#pragma unroll
        for (int i = 0; i < 8; i++) {
            float4 v = pf[i];
            __nv_bfloat16 hx = __float2bfloat16(v.x), hy = __float2bfloat16(v.y);
            __nv_bfloat16 hz = __float2bfloat16(v.z), hw = __float2bfloat16(v.w);
            *(uint2*)(sm + SAH_OFF + aDstByte + i * 8) =
                make_uint2(bfbits(hx) | (bfbits(hy) << 16), bfbits(hz) | (bfbits(hw) << 16));
            __nv_bfloat16 lx = __float2bfloat16(v.x - __bfloat162float(hx));
            __nv_bfloat16 ly = __float2bfloat16(v.y - __bfloat162float(hy));
            __nv_bfloat16 lz = __float2bfloat16(v.z - __bfloat162float(hz));
            __nv_bfloat16 lw = __float2bfloat16(v.w - __bfloat162float(hw));
            *(uint2*)(sm + SAL_OFF + aDstByte + i * 8) =
                make_uint2(bfbits(lx) | (bfbits(ly) << 16), bfbits(lz) | (bfbits(lw) << 16));
        }
        // ---- store B ----
#pragma unroll
        for (int j = 0; j < 4; j++) {
            int lin = t + j * 256;
            int n = lin >> 4, q = lin & 15;
            uint32_t dst = (uint32_t)(n * (SA_STRIDE * 2) + q * 8);
            *(uint2*)(sm + SBH_OFF + dst) = bh[j];
            *(uint2*)(sm + SBL_OFF + dst) = bl[j];
        }
        __syncthreads();

        // ---- prefetch next A chunk (overlaps MMA phase) ----
        if (kc < 15) {
#pragma unroll
            for (int i = 0; i < 8; i++)
                pf[i] = avalid ? __ldg(xrow + (kc + 1) * 16 + ahalf * 8 + i)
                               : make_float4(0.f, 0.f, 0.f, 0.f);
        }

        // ---- compute: 4 k16 steps x 8 ntiles x 3 passes ----
#pragma unroll
        for (int ks = 0; ks < 4; ks++) {
            uint32_t ah[4], al[4];
            LDSM4(ah, aLd + SAH_OFF + ks * 32);
            LDSM4(al, aLd + SAL_OFF + ks * 32);
#pragma unroll
            for (int jp = 0; jp < 4; jp++) {
                uint32_t vh[4], vl[4];
                LDSM4(vh, bLd + SBH_OFF + jp * (16 * SA_STRIDE * 2) + ks * 32);
                LDSM4(vl, bLd + SBL_OFF + jp * (16 * SA_STRIDE * 2) + ks * 32);
                mma16816(acc[2 * jp],     ah, vh[0], vh[1]);
                mma16816(acc[2 * jp],     ah, vl[0], vl[1]);
                mma16816(acc[2 * jp],     al, vh[0], vh[1]);
                mma16816(acc[2 * jp + 1], ah, vh[2], vh[3]);
                mma16816(acc[2 * jp + 1], ah, vl[2], vl[3]);
                mma16816(acc[2 * jp + 1], al, vh[2], vh[3]);
            }
        }
        __syncthreads();
    }

    // ---- epilogue ----
    const int g = lane >> 2, tig = lane & 3;
    const int r0 = m0 + w * 16 + g;
    const int r1 = r0 + 8;
#pragma unroll
    for (int nt = 0; nt < 8; nt++) {
        int c = nt * 8 + tig * 2;
        if (r0 < NN) *(float2*)(g_H1 + (size_t)r0 * 64 + c) = make_float2(acc[nt][0], acc[nt][1]);
        if (r1 < NN) *(float2*)(g_H1 + (size_t)r1 * 64 + c) = make_float2(acc[nt][2], acc[nt][3]);
    }
}

// ---------------- gather layer 1 (warp per node) + relu + bias ----------------
__global__ void __launch_bounds__(256) k_gather1(const float* __restrict__ b1) {
    const int w = threadIdx.x >> 5, lane = threadIdx.x & 31;
    const int n = blockIdx.x * 8 + w;
    if (n >= NN) return;
    float di = __ldg(g_dinv + n);
    float2 acc = __ldg((const float2*)(g_H1 + (size_t)n * 64) + lane);
    acc.x *= di * di; acc.y *= di * di;

    const int start = __ldg(g_rowptr + n);
    const int cnt   = __ldg(g_deg + n);
    const int2* ep = g_edge + start;
    int i = 0;
    for (; i + 4 <= cnt; i += 4) {
        int2 e0 = __ldg(ep + i),     e1 = __ldg(ep + i + 1);
        int2 e2 = __ldg(ep + i + 2), e3 = __ldg(ep + i + 3);
        float2 v0 = __ldg((const float2*)(g_H1 + (size_t)e0.x * 64) + lane);
        float2 v1 = __ldg((const float2*)(g_H1 + (size_t)e1.x * 64) + lane);
        float2 v2 = __ldg((const float2*)(g_H1 + (size_t)e2.x * 64) + lane);
        float2 v3 = __ldg((const float2*)(g_H1 + (size_t)e3.x * 64) + lane);
        float w0 = __int_as_float(e0.y), w1 = __int_as_float(e1.y);
        float w2 = __int_as_float(e2.y), w3 = __int_as_float(e3.y);
        acc.x = fmaf(w0, v0.x, acc.x); acc.y = fmaf(w0, v0.y, acc.y);
        acc.x = fmaf(w1, v1.x, acc.x); acc.y = fmaf(w1, v1.y, acc.y);
        acc.x = fmaf(w2, v2.x, acc.x); acc.y = fmaf(w2, v2.y, acc.y);
        acc.x = fmaf(w3, v3.x, acc.x); acc.y = fmaf(w3, v3.y, acc.y);
    }
    for (; i < cnt; i++) {
        int2 e = __ldg(ep + i);
        float2 v = __ldg((const float2*)(g_H1 + (size_t)e.x * 64) + lane);
        float wt = __int_as_float(e.y);
        acc.x = fmaf(wt, v.x, acc.x); acc.y = fmaf(wt, v.y, acc.y);
    }
    float2 b = __ldg((const float2*)b1 + lane);
    float2 o = make_float2(fmaxf(acc.x + b.x, 0.f), fmaxf(acc.y + b.y, 0.f));
    *(float2*)(g_O1 + (size_t)n * 64 + lane * 2) = o;
}

// ---------------- GEMM2: O1 @ W2 (bias already applied in gather1) ----------------
__global__ void __launch_bounds__(256) k_gemm2(const float* __restrict__ W2) {
    __shared__ float sW[HID * NC];
    for (int i = threadIdx.x; i < HID * NC; i += blockDim.x) sW[i] = W2[i];
    __syncthreads();
    int r = blockIdx.x * blockDim.x + threadIdx.x;
    if (r >= NN) return;
    float acc[NC];
#pragma unroll
    for (int c = 0; c < NC; c++) acc[c] = 0.f;
    const float4* a4 = (const float4*)(g_O1 + (size_t)r * HID);
#pragma unroll
    for (int kk = 0; kk < 16; kk++) {
        float4 av = __ldg(a4 + kk);
#pragma unroll
        for (int c = 0; c < NC; c++) {
            acc[c] = fmaf(av.x, sW[(kk * 4 + 0) * NC + c], acc[c]);
            acc[c] = fmaf(av.y, sW[(kk * 4 + 1) * NC + c], acc[c]);
            acc[c] = fmaf(av.z, sW[(kk * 4 + 2) * NC + c], acc[c]);
            acc[c] = fmaf(av.w, sW[(kk * 4 + 3) * NC + c], acc[c]);
        }
    }
    float* o = g_H2 + (size_t)r * NC;
#pragma unroll
    for (int c = 0; c < NC; c++) o[c] = acc[c];
}

// ---------------- gather layer 2 + bias + log_softmax (warp per node) ----------------
__global__ void __launch_bounds__(256) k_gather2(const float* __restrict__ b2,
                                                 float* __restrict__ out) {
    const int w = threadIdx.x >> 5, lane = threadIdx.x & 31;
    const int n = blockIdx.x * 8 + w;
    if (n >= NN) return;
    const bool act = lane < 20;  // 20 lanes x float2 = 40 cols
    float di = __ldg(g_dinv + n);
    float2 acc = make_float2(0.f, 0.f);
    if (act) {
        acc = __ldg((const float2*)(g_H2 + (size_t)n * NC) + lane);
        acc.x *= di * di; acc.y *= di * di;
    }
    const int start = __ldg(g_rowptr + n);
    const int cnt   = __ldg(g_deg + n);
    const int2* ep = g_edge + start;
    int i = 0;
    for (; i + 4 <= cnt; i += 4) {
        int2 e0 = __ldg(ep + i),     e1 = __ldg(ep + i + 1);
        int2 e2 = __ldg(ep + i + 2), e3 = __ldg(ep + i + 3);
        if (act) {
            float2 v0 = __ldg((const float2*)(g_H2 + (size_t)e0.x * NC) + lane);
            float2 v1 = __ldg((const float2*)(g_H2 + (size_t)e1.x * NC) + lane);
            float2 v2 = __ldg((const float2*)(g_H2 + (size_t)e2.x * NC) + lane);
            float2 v3 = __ldg((const float2*)(g_H2 + (size_t)e3.x * NC) + lane);
            float w0 = __int_as_float(e0.y), w1 = __int_as_float(e1.y);
            float w2 = __int_as_float(e2.y), w3 = __int_as_float(e3.y);
            acc.x = fmaf(w0, v0.x, acc.x); acc.y = fmaf(w0, v0.y, acc.y);
            acc.x = fmaf(w1, v1.x, acc.x); acc.y = fmaf(w1, v1.y, acc.y);
            acc.x = fmaf(w2, v2.x, acc.x); acc.y = fmaf(w2, v2.y, acc.y);
            acc.x = fmaf(w3, v3.x, acc.x); acc.y = fmaf(w3, v3.y, acc.y);
        }
    }
    for (; i < cnt; i++) {
        int2 e = __ldg(ep + i);
        if (act) {
            float2 v = __ldg((const float2*)(g_H2 + (size_t)e.x * NC) + lane);
            float wt = __int_as_float(e.y);
            acc.x = fmaf(wt, v.x, acc.x); acc.y = fmaf(wt, v.y, acc.y);
        }
    }
    // bias
    float2 z = make_float2(-CUDART_INF_F, -CUDART_INF_F);
    if (act) {
        float2 b = __ldg((const float2*)b2 + lane);
        z = make_float2(acc.x + b.x, acc.y + b.y);
    }
    // warp log-softmax over 40 values
    float m = fmaxf(z.x, z.y);
#pragma unroll
    for (int off = 16; off; off >>= 1) m = fmaxf(m, __shfl_xor_sync(0xffffffffu, m, off));
    float s = act ? (__expf(z.x - m) + __expf(z.y - m)) : 0.f;
#pragma unroll
    for (int off = 16; off; off >>= 1) s += __shfl_xor_sync(0xffffffffu, s, off);
    float l = m + __logf(s);
    if (act)
        *(float2*)(out + (size_t)n * NC + lane * 2) = make_float2(z.x - l, z.y - l);
}

// ---------------- launch ----------------
extern "C" void kernel_launch(void* const* d_in, const int* in_sizes, int n_in,
                              void* d_out, int out_size) {
    const float* x  = (const float*)d_in[0];
    const int*   ei = (const int*)d_in[1];
    const float* W1 = (const float*)d_in[2];
    const float* b1 = (const float*)d_in[3];
    const float* W2 = (const float*)d_in[4];
    const float* b2 = (const float*)d_in[5];
    const int* row = ei;         // sources
    const int* col = ei + NE;    // targets
    float* out = (float*)d_out;

    static bool attr_set = false;
    if (!attr_set) {
        cudaFuncSetAttribute(k_gemm1, cudaFuncAttributeMaxDynamicSharedMemorySize, SM_TOTAL);
        attr_set = true;
    }

    // prep + CSR build
    k_deg_init<<<(NN + 255) / 256, 256>>>();
    k_hist<<<(NE + 255) / 256, 256>>>(col);
    k_dinv<<<(NN + 255) / 256, 256>>>();
    k_wsplit<<<(DF * HID + 255) / 256, 256>>>(W1);
    k_scanA<<<SCAN_NB, 256>>>();
    k_scanB<<<1, 256>>>();
    k_scanC<<<SCAN_NB, 256>>>();
    k_fill<<<(NE + 255) / 256, 256>>>(row, col);

    // layer 1
    k_gemm1<<<(NN + 127) / 128, 256, SM_TOTAL>>>(x);
    k_gather1<<<(NN + 7) / 8, 256>>>(b1);

    // layer 2
    k_gemm2<<<(NN + 255) / 256, 256>>>(W2);
    k_gather2<<<(NN + 7) / 8, 256>>>(b2, out);
}

// round 4
// speedup vs baseline: 1.6038x; 1.2310x over previous
#include <cuda_runtime.h>
#include <cuda_bf16.h>
#include <cstdint>
#include <math_constants.h>

// ---------------- problem constants ----------------
static constexpr int NN  = 40000;     // nodes
static constexpr int NE  = 1280000;   // edges
static constexpr int DF  = 1024;      // input feat
static constexpr int HID = 64;        // hidden
static constexpr int NC  = 40;        // classes

// ---------------- device scratch ----------------
__device__ float g_H1[(size_t)NN * HID];   // x @ W1
__device__ float g_O1[(size_t)NN * HID];   // relu(A_hat @ H1 + b1)
__device__ float g_H2[(size_t)NN * NC];    // O1 @ W2
__device__ float g_dinv[NN];
__device__ int   g_deg[NN];                // in-degree (no self loop)
__device__ int   g_rowptr[NN];             // CSR start per node
__device__ int   g_cursor[NN];
__device__ int   g_rowtmp[NN];             // inclusive scan, pre-base
__device__ int   g_bsum[160];
__device__ int   g_bbase[160];
__device__ int2  g_edge[NE];               // (src, weight-bits) sorted by dst
__device__ __nv_bfloat16 g_W1h[(size_t)HID * DF];  // W1^T hi, [n][k]
__device__ __nv_bfloat16 g_W1l[(size_t)HID * DF];  // W1^T lo, [n][k]

// ---------------- helpers ----------------
__device__ __forceinline__ uint32_t smem_to_u32(const void* p) {
    uint32_t a;
    asm("{ .reg .u64 t; cvta.to.shared.u64 t, %1; cvt.u32.u64 %0, t; }" : "=r"(a) : "l"(p));
    return a;
}
__device__ __forceinline__ uint32_t bfbits(__nv_bfloat16 h) {
    return (uint32_t)__bfloat16_as_ushort(h);
}
#define LDSM4(r, addr) \
    asm volatile("ldmatrix.sync.aligned.m8n8.x4.shared.b16 {%0,%1,%2,%3}, [%4];" \
                 : "=r"((r)[0]), "=r"((r)[1]), "=r"((r)[2]), "=r"((r)[3]) : "r"(addr))
__device__ __forceinline__ void mma16816(float* c, const uint32_t* a, uint32_t b0, uint32_t b1) {
    asm volatile(
        "mma.sync.aligned.m16n8k16.row.col.f32.bf16.bf16.f32 "
        "{%0,%1,%2,%3}, {%4,%5,%6,%7}, {%8,%9}, {%0,%1,%2,%3};"
        : "+f"(c[0]), "+f"(c[1]), "+f"(c[2]), "+f"(c[3])
        : "r"(a[0]), "r"(a[1]), "r"(a[2]), "r"(a[3]), "r"(b0), "r"(b1));
}

// ---------------- prep ----------------
__global__ void k_hist(const int* __restrict__ col) {
    int e = blockIdx.x * blockDim.x + threadIdx.x;
    if (e < NE) atomicAdd(&g_deg[col[e]], 1);
}
__global__ void k_wsplit(const float* __restrict__ W1) {
    int idx = blockIdx.x * blockDim.x + threadIdx.x;
    if (idx >= DF * HID) return;
    int k = idx >> 6, n = idx & 63;
    float w = W1[idx];
    __nv_bfloat16 hi = __float2bfloat16(w);
    float lo = w - __bfloat162float(hi);
    g_W1h[(size_t)n * DF + k] = hi;
    g_W1l[(size_t)n * DF + k] = __float2bfloat16(lo);
}

// ---------------- CSR build: 3-phase scan + fill ----------------
static constexpr int SCAN_NB = (NN + 255) / 256;  // 157
__global__ void k_scanA() {
    __shared__ int s[256];
    int i = blockIdx.x * 256 + threadIdx.x;
    int v = (i < NN) ? g_deg[i] : 0;
    s[threadIdx.x] = v;
    __syncthreads();
#pragma unroll
    for (int off = 1; off < 256; off <<= 1) {
        int t = (threadIdx.x >= off) ? s[threadIdx.x - off] : 0;
        __syncthreads();
        s[threadIdx.x] += t;
        __syncthreads();
    }
    if (i < NN) g_rowtmp[i] = s[threadIdx.x];
    if (threadIdx.x == 255) g_bsum[blockIdx.x] = s[255];
}
__global__ void k_scanB() {
    __shared__ int s[256];
    int v = (threadIdx.x < SCAN_NB) ? g_bsum[threadIdx.x] : 0;
    s[threadIdx.x] = v;
    __syncthreads();
#pragma unroll
    for (int off = 1; off < 256; off <<= 1) {
        int t = (threadIdx.x >= off) ? s[threadIdx.x - off] : 0;
        __syncthreads();
        s[threadIdx.x] += t;
        __syncthreads();
    }
    if (threadIdx.x < SCAN_NB) g_bbase[threadIdx.x] = s[threadIdx.x] - v;  // exclusive
}
__global__ void k_scanC() {  // rowptr/cursor + dinv fused
    int i = blockIdx.x * 256 + threadIdx.x;
    if (i >= NN) return;
    int d = g_deg[i];
    int start = g_rowtmp[i] + g_bbase[blockIdx.x] - d;
    g_rowptr[i] = start;
    g_cursor[i] = start;
    g_dinv[i] = rsqrtf((float)(d + 1));  // +1 self loop
}
__global__ void k_fill(const int* __restrict__ row, const int* __restrict__ col) {
    int e = blockIdx.x * blockDim.x + threadIdx.x;
    if (e >= NE) return;
    int r = __ldg(row + e), c = __ldg(col + e);
    int p = atomicAdd(&g_cursor[c], 1);
    float w = __ldg(g_dinv + r) * __ldg(g_dinv + c);
    g_edge[p] = make_int2(r, __float_as_int(w));
}

// ---------------- GEMM1: mma.sync bf16 hi/lo compensated, coalesced A ----------------
static constexpr int SA_STRIDE = 72;                     // bf16 elems per row
static constexpr int SAH_OFF = 0;
static constexpr int SAL_OFF = 128 * SA_STRIDE * 2;      // 18432
static constexpr int SBH_OFF = SAL_OFF * 2;              // 36864
static constexpr int SBL_OFF = SBH_OFF + 64 * SA_STRIDE * 2;  // 46080
static constexpr int SM_TOTAL = SBL_OFF + 64 * SA_STRIDE * 2; // 55296

__global__ void __launch_bounds__(256, 2) k_gemm1(const float* __restrict__ x) {
    extern __shared__ char sm[];
    const uint32_t smb = smem_to_u32(sm);
    const int t = threadIdx.x;
    const int lane = t & 31, w = t >> 5;
    const int m0 = blockIdx.x * 128;

    // Coalesced A mapping: thread t -> rows {t/16 + 16i}, fixed 16B col block c4=t&15.
    // Warp instr covers 2 rows x 256B contiguous (4 lines) - ideal wavefronts.
    const int r0t = t >> 4;
    const int c4  = t & 15;
    const float4* xb = (const float4*)x;   // global float4 base
    bool rv[8];
    size_t rbase[8];
    uint32_t aDst[8];
#pragma unroll
    for (int i = 0; i < 8; i++) {
        int rowg = m0 + r0t + 16 * i;
        rv[i] = rowg < NN;
        rbase[i] = (size_t)rowg * 256 + c4;        // float4 index (row*1024f/4)
        aDst[i] = (uint32_t)((r0t + 16 * i) * (SA_STRIDE * 2) + c4 * 8);
    }

    const uint32_t aLd = smb +
        (uint32_t)((w * 16 + (lane & 7) + ((lane >> 3) & 1) * 8) * (SA_STRIDE * 2) +
                   (lane >> 4) * 16);
    const uint32_t bLd = smb +
        (uint32_t)((((lane >> 4) * 8) + (lane & 7)) * (SA_STRIDE * 2) +
                   ((lane >> 3) & 1) * 16);

    float acc[8][4];
#pragma unroll
    for (int j = 0; j < 8; j++)
#pragma unroll
        for (int q = 0; q < 4; q++) acc[j][q] = 0.f;

    float4 pf[8];
#pragma unroll
    for (int i = 0; i < 8; i++)
        pf[i] = rv[i] ? __ldg(xb + rbase[i]) : make_float4(0.f, 0.f, 0.f, 0.f);

    for (int kc = 0; kc < 16; kc++) {
        // ---- B global loads first (latency overlaps A convert ALU) ----
        uint2 bh[4], bl[4];
#pragma unroll
        for (int j = 0; j < 4; j++) {
            int lin = t + j * 256;
            int n = lin >> 4, q = lin & 15;
            size_t src = (size_t)n * DF + kc * 64 + q * 4;
            bh[j] = __ldg((const uint2*)(g_W1h + src));
            bl[j] = __ldg((const uint2*)(g_W1l + src));
        }
        // ---- convert prefetched A: f32 -> bf16 hi/lo ----
#pragma unroll
        for (int i = 0; i < 8; i++) {
            float4 v = pf[i];
            __nv_bfloat16 hx = __float2bfloat16(v.x), hy = __float2bfloat16(v.y);
            __nv_bfloat16 hz = __float2bfloat16(v.z), hw = __float2bfloat16(v.w);
            *(uint2*)(sm + SAH_OFF + aDst[i]) =
                make_uint2(bfbits(hx) | (bfbits(hy) << 16), bfbits(hz) | (bfbits(hw) << 16));
            __nv_bfloat16 lx = __float2bfloat16(v.x - __bfloat162float(hx));
            __nv_bfloat16 ly = __float2bfloat16(v.y - __bfloat162float(hy));
            __nv_bfloat16 lz = __float2bfloat16(v.z - __bfloat162float(hz));
            __nv_bfloat16 lw = __float2bfloat16(v.w - __bfloat162float(hw));
            *(uint2*)(sm + SAL_OFF + aDst[i]) =
                make_uint2(bfbits(lx) | (bfbits(ly) << 16), bfbits(lz) | (bfbits(lw) << 16));
        }
        // ---- store B ----
#pragma unroll
        for (int j = 0; j < 4; j++) {
            int lin = t + j * 256;
            int n = lin >> 4, q = lin & 15;
            uint32_t dst = (uint32_t)(n * (SA_STRIDE * 2) + q * 8);
            *(uint2*)(sm + SBH_OFF + dst) = bh[j];
            *(uint2*)(sm + SBL_OFF + dst) = bl[j];
        }
        __syncthreads();

        // ---- prefetch next A chunk (overlaps MMA phase) ----
        if (kc < 15) {
#pragma unroll
            for (int i = 0; i < 8; i++)
                pf[i] = rv[i] ? __ldg(xb + rbase[i] + (kc + 1) * 16)
                              : make_float4(0.f, 0.f, 0.f, 0.f);
        }

        // ---- compute: 4 k16 steps x 8 ntiles x 3 passes ----
#pragma unroll
        for (int ks = 0; ks < 4; ks++) {
            uint32_t ah[4], al[4];
            LDSM4(ah, aLd + SAH_OFF + ks * 32);
            LDSM4(al, aLd + SAL_OFF + ks * 32);
#pragma unroll
            for (int jp = 0; jp < 4; jp++) {
                uint32_t vh[4], vl[4];
                LDSM4(vh, bLd + SBH_OFF + jp * (16 * SA_STRIDE * 2) + ks * 32);
                LDSM4(vl, bLd + SBL_OFF + jp * (16 * SA_STRIDE * 2) + ks * 32);
                mma16816(acc[2 * jp],     ah, vh[0], vh[1]);
                mma16816(acc[2 * jp],     ah, vl[0], vl[1]);
                mma16816(acc[2 * jp],     al, vh[0], vh[1]);
                mma16816(acc[2 * jp + 1], ah, vh[2], vh[3]);
                mma16816(acc[2 * jp + 1], ah, vl[2], vl[3]);
                mma16816(acc[2 * jp + 1], al, vh[2], vh[3]);
            }
        }
        __syncthreads();
    }

    // ---- epilogue ----
    const int g = lane >> 2, tig = lane & 3;
    const int r0 = m0 + w * 16 + g;
    const int r1 = r0 + 8;
#pragma unroll
    for (int nt = 0; nt < 8; nt++) {
        int c = nt * 8 + tig * 2;
        if (r0 < NN) *(float2*)(g_H1 + (size_t)r0 * 64 + c) = make_float2(acc[nt][0], acc[nt][1]);
        if (r1 < NN) *(float2*)(g_H1 + (size_t)r1 * 64 + c) = make_float2(acc[nt][2], acc[nt][3]);
    }
}

// ---------------- gather layer 1 (warp per node, MLP 8) + relu + bias ----------------
__global__ void __launch_bounds__(256) k_gather1(const float* __restrict__ b1) {
    const int w = threadIdx.x >> 5, lane = threadIdx.x & 31;
    const int n = blockIdx.x * 8 + w;
    if (n >= NN) return;
    float di = __ldg(g_dinv + n);
    float2 acc = __ldg((const float2*)(g_H1 + (size_t)n * 64) + lane);
    acc.x *= di * di; acc.y *= di * di;

    const int start = __ldg(g_rowptr + n);
    const int cnt   = __ldg(g_deg + n);
    const int2* ep = g_edge + start;
    int i = 0;
    for (; i + 8 <= cnt; i += 8) {
        int2 e[8];
#pragma unroll
        for (int u = 0; u < 8; u++) e[u] = __ldg(ep + i + u);
        float2 v[8];
#pragma unroll
        for (int u = 0; u < 8; u++)
            v[u] = __ldg((const float2*)(g_H1 + (size_t)e[u].x * 64) + lane);
#pragma unroll
        for (int u = 0; u < 8; u++) {
            float wt = __int_as_float(e[u].y);
            acc.x = fmaf(wt, v[u].x, acc.x);
            acc.y = fmaf(wt, v[u].y, acc.y);
        }
    }
    for (; i < cnt; i++) {
        int2 e = __ldg(ep + i);
        float2 v = __ldg((const float2*)(g_H1 + (size_t)e.x * 64) + lane);
        float wt = __int_as_float(e.y);
        acc.x = fmaf(wt, v.x, acc.x); acc.y = fmaf(wt, v.y, acc.y);
    }
    float2 b = __ldg((const float2*)b1 + lane);
    float2 o = make_float2(fmaxf(acc.x + b.x, 0.f), fmaxf(acc.y + b.y, 0.f));
    *(float2*)(g_O1 + (size_t)n * 64 + lane * 2) = o;
}

// ---------------- GEMM2: O1 @ W2 (bias applied in gather1) ----------------
__global__ void __launch_bounds__(256) k_gemm2(const float* __restrict__ W2) {
    __shared__ float sW[HID * NC];
    for (int i = threadIdx.x; i < HID * NC; i += blockDim.x) sW[i] = W2[i];
    __syncthreads();
    int r = blockIdx.x * blockDim.x + threadIdx.x;
    if (r >= NN) return;
    float acc[NC];
#pragma unroll
    for (int c = 0; c < NC; c++) acc[c] = 0.f;
    const float4* a4 = (const float4*)(g_O1 + (size_t)r * HID);
#pragma unroll
    for (int kk = 0; kk < 16; kk++) {
        float4 av = __ldg(a4 + kk);
#pragma unroll
        for (int c = 0; c < NC; c++) {
            acc[c] = fmaf(av.x, sW[(kk * 4 + 0) * NC + c], acc[c]);
            acc[c] = fmaf(av.y, sW[(kk * 4 + 1) * NC + c], acc[c]);
            acc[c] = fmaf(av.z, sW[(kk * 4 + 2) * NC + c], acc[c]);
            acc[c] = fmaf(av.w, sW[(kk * 4 + 3) * NC + c], acc[c]);
        }
    }
    float* o = g_H2 + (size_t)r * NC;
#pragma unroll
    for (int c = 0; c < NC; c++) o[c] = acc[c];
}

// ---------------- gather layer 2 + bias + log_softmax (warp per node, MLP 8) ----------------
__global__ void __launch_bounds__(256) k_gather2(const float* __restrict__ b2,
                                                 float* __restrict__ out) {
    const int w = threadIdx.x >> 5, lane = threadIdx.x & 31;
    const int n = blockIdx.x * 8 + w;
    if (n >= NN) return;
    const bool act = lane < 20;  // 20 lanes x float2 = 40 cols
    float di = __ldg(g_dinv + n);
    float2 acc = make_float2(0.f, 0.f);
    if (act) {
        acc = __ldg((const float2*)(g_H2 + (size_t)n * NC) + lane);
        acc.x *= di * di; acc.y *= di * di;
    }
    const int start = __ldg(g_rowptr + n);
    const int cnt   = __ldg(g_deg + n);
    const int2* ep = g_edge + start;
    int i = 0;
    for (; i + 8 <= cnt; i += 8) {
        int2 e[8];
#pragma unroll
        for (int u = 0; u < 8; u++) e[u] = __ldg(ep + i + u);
        if (act) {
            float2 v[8];
#pragma unroll
            for (int u = 0; u < 8; u++)
                v[u] = __ldg((const float2*)(g_H2 + (size_t)e[u].x * NC) + lane);
#pragma unroll
            for (int u = 0; u < 8; u++) {
                float wt = __int_as_float(e[u].y);
                acc.x = fmaf(wt, v[u].x, acc.x);
                acc.y = fmaf(wt, v[u].y, acc.y);
            }
        }
    }
    for (; i < cnt; i++) {
        int2 e = __ldg(ep + i);
        if (act) {
            float2 v = __ldg((const float2*)(g_H2 + (size_t)e.x * NC) + lane);
            float wt = __int_as_float(e.y);
            acc.x = fmaf(wt, v.x, acc.x); acc.y = fmaf(wt, v.y, acc.y);
        }
    }
    float2 z = make_float2(-CUDART_INF_F, -CUDART_INF_F);
    if (act) {
        float2 b = __ldg((const float2*)b2 + lane);
        z = make_float2(acc.x + b.x, acc.y + b.y);
    }
    float m = fmaxf(z.x, z.y);
#pragma unroll
    for (int off = 16; off; off >>= 1) m = fmaxf(m, __shfl_xor_sync(0xffffffffu, m, off));
    float s = act ? (__expf(z.x - m) + __expf(z.y - m)) : 0.f;
#pragma unroll
    for (int off = 16; off; off >>= 1) s += __shfl_xor_sync(0xffffffffu, s, off);
    float l = m + __logf(s);
    if (act)
        *(float2*)(out + (size_t)n * NC + lane * 2) = make_float2(z.x - l, z.y - l);
}

// ---------------- launch ----------------
extern "C" void kernel_launch(void* const* d_in, const int* in_sizes, int n_in,
                              void* d_out, int out_size) {
    const float* x  = (const float*)d_in[0];
    const int*   ei = (const int*)d_in[1];
    const float* W1 = (const float*)d_in[2];
    const float* b1 = (const float*)d_in[3];
    const float* W2 = (const float*)d_in[4];
    const float* b2 = (const float*)d_in[5];
    const int* row = ei;         // sources
    const int* col = ei + NE;    // targets
    float* out = (float*)d_out;

    static void* deg_ptr = nullptr;
    if (!deg_ptr) {  // resolved on the (non-captured) correctness call
        cudaFuncSetAttribute(k_gemm1, cudaFuncAttributeMaxDynamicSharedMemorySize, SM_TOTAL);
        cudaGetSymbolAddress(&deg_ptr, g_deg);
    }

    // prep + CSR build
    cudaMemsetAsync(deg_ptr, 0, NN * sizeof(int));
    k_hist<<<(NE + 255) / 256, 256>>>(col);
    k_wsplit<<<(DF * HID + 255) / 256, 256>>>(W1);
    k_scanA<<<SCAN_NB, 256>>>();
    k_scanB<<<1, 256>>>();
    k_scanC<<<SCAN_NB, 256>>>();
    k_fill<<<(NE + 255) / 256, 256>>>(row, col);

    // layer 1
    k_gemm1<<<(NN + 127) / 128, 256, SM_TOTAL>>>(x);
    k_gather1<<<(NN + 7) / 8, 256>>>(b1);

    // layer 2
    k_gemm2<<<(NN + 255) / 256, 256>>>(W2);
    k_gather2<<<(NN + 7) / 8, 256>>>(b2, out);
}

// round 5
// speedup vs baseline: 1.9119x; 1.1921x over previous
#include <cuda_runtime.h>
#include <cuda_bf16.h>
#include <cstdint>
#include <math_constants.h>

// ---------------- problem constants ----------------
static constexpr int NN  = 40000;     // nodes
static constexpr int NE  = 1280000;   // edges
static constexpr int DF  = 1024;      // input feat
static constexpr int HID = 64;        // hidden
static constexpr int NC  = 40;        // classes

// ---------------- device scratch ----------------
__device__ float g_H1[(size_t)NN * HID];   // x @ W1
__device__ float g_H2[(size_t)NN * NC];    // relu(agg1 + b1) @ W2
__device__ float g_dinv[NN];
__device__ int   g_deg[NN];                // in-degree (no self loop)
__device__ int   g_rowptr[NN];             // CSR start per node
__device__ int   g_cursor[NN];
__device__ int   g_rowtmp[NN];             // inclusive scan, pre-base
__device__ int   g_bsum[160];
__device__ int   g_bbase[160];
__device__ int2  g_edge[NE];               // (src, weight-bits) sorted by dst
__device__ __nv_bfloat16 g_W1h[(size_t)HID * DF];  // W1^T hi, [n][k]
__device__ __nv_bfloat16 g_W1l[(size_t)HID * DF];  // W1^T lo, [n][k]

// ---------------- helpers ----------------
__device__ __forceinline__ uint32_t smem_to_u32(const void* p) {
    uint32_t a;
    asm("{ .reg .u64 t; cvta.to.shared.u64 t, %1; cvt.u32.u64 %0, t; }" : "=r"(a) : "l"(p));
    return a;
}
__device__ __forceinline__ uint32_t bfbits(__nv_bfloat16 h) {
    return (uint32_t)__bfloat16_as_ushort(h);
}
#define LDSM4(r, addr) \
    asm volatile("ldmatrix.sync.aligned.m8n8.x4.shared.b16 {%0,%1,%2,%3}, [%4];" \
                 : "=r"((r)[0]), "=r"((r)[1]), "=r"((r)[2]), "=r"((r)[3]) : "r"(addr))
__device__ __forceinline__ void mma16816(float* c, const uint32_t* a, uint32_t b0, uint32_t b1) {
    asm volatile(
        "mma.sync.aligned.m16n8k16.row.col.f32.bf16.bf16.f32 "
        "{%0,%1,%2,%3}, {%4,%5,%6,%7}, {%8,%9}, {%0,%1,%2,%3};"
        : "+f"(c[0]), "+f"(c[1]), "+f"(c[2]), "+f"(c[3])
        : "r"(a[0]), "r"(a[1]), "r"(a[2]), "r"(a[3]), "r"(b0), "r"(b1));
}

// ---------------- prep ----------------
__global__ void k_hist(const int* __restrict__ col) {
    int e = blockIdx.x * blockDim.x + threadIdx.x;
    if (e < NE) atomicAdd(&g_deg[col[e]], 1);
}
__global__ void k_wsplit(const float* __restrict__ W1) {
    int idx = blockIdx.x * blockDim.x + threadIdx.x;
    if (idx >= DF * HID) return;
    int k = idx >> 6, n = idx & 63;
    float w = W1[idx];
    __nv_bfloat16 hi = __float2bfloat16(w);
    float lo = w - __bfloat162float(hi);
    g_W1h[(size_t)n * DF + k] = hi;
    g_W1l[(size_t)n * DF + k] = __float2bfloat16(lo);
}

// ---------------- CSR build: 3-phase scan + fill ----------------
static constexpr int SCAN_NB = (NN + 255) / 256;  // 157
__global__ void k_scanA() {
    __shared__ int s[256];
    int i = blockIdx.x * 256 + threadIdx.x;
    int v = (i < NN) ? g_deg[i] : 0;
    s[threadIdx.x] = v;
    __syncthreads();
#pragma unroll
    for (int off = 1; off < 256; off <<= 1) {
        int t = (threadIdx.x >= off) ? s[threadIdx.x - off] : 0;
        __syncthreads();
        s[threadIdx.x] += t;
        __syncthreads();
    }
    if (i < NN) g_rowtmp[i] = s[threadIdx.x];
    if (threadIdx.x == 255) g_bsum[blockIdx.x] = s[255];
}
__global__ void k_scanB() {
    __shared__ int s[256];
    int v = (threadIdx.x < SCAN_NB) ? g_bsum[threadIdx.x] : 0;
    s[threadIdx.x] = v;
    __syncthreads();
#pragma unroll
    for (int off = 1; off < 256; off <<= 1) {
        int t = (threadIdx.x >= off) ? s[threadIdx.x - off] : 0;
        __syncthreads();
        s[threadIdx.x] += t;
        __syncthreads();
    }
    if (threadIdx.x < SCAN_NB) g_bbase[threadIdx.x] = s[threadIdx.x] - v;  // exclusive
}
__global__ void k_scanC() {  // rowptr/cursor + dinv fused
    int i = blockIdx.x * 256 + threadIdx.x;
    if (i >= NN) return;
    int d = g_deg[i];
    int start = g_rowtmp[i] + g_bbase[blockIdx.x] - d;
    g_rowptr[i] = start;
    g_cursor[i] = start;
    g_dinv[i] = rsqrtf((float)(d + 1));  // +1 self loop
}
__global__ void k_fill(const int* __restrict__ row, const int* __restrict__ col) {
    int e = blockIdx.x * blockDim.x + threadIdx.x;
    if (e >= NE) return;
    int r = __ldg(row + e), c = __ldg(col + e);
    int p = atomicAdd(&g_cursor[c], 1);
    float w = __ldg(g_dinv + r) * __ldg(g_dinv + c);
    g_edge[p] = make_int2(r, __float_as_int(w));
}

// ---------------- GEMM1: mma.sync bf16 hi/lo compensated, coalesced A ----------------
static constexpr int SA_STRIDE = 72;                     // bf16 elems per row
static constexpr int SAH_OFF = 0;
static constexpr int SAL_OFF = 128 * SA_STRIDE * 2;      // 18432
static constexpr int SBH_OFF = SAL_OFF * 2;              // 36864
static constexpr int SBL_OFF = SBH_OFF + 64 * SA_STRIDE * 2;  // 46080
static constexpr int SM_TOTAL = SBL_OFF + 64 * SA_STRIDE * 2; // 55296

__global__ void __launch_bounds__(256, 2) k_gemm1(const float* __restrict__ x) {
    extern __shared__ char sm[];
    const uint32_t smb = smem_to_u32(sm);
    const int t = threadIdx.x;
    const int lane = t & 31, w = t >> 5;
    const int m0 = blockIdx.x * 128;

    // Coalesced A mapping: thread t -> rows {t/16 + 16i}, fixed 16B col block c4=t&15.
    const int r0t = t >> 4;
    const int c4  = t & 15;
    const float4* xb = (const float4*)x;
    bool rv[8];
    size_t rbase[8];
    uint32_t aDst[8];
#pragma unroll
    for (int i = 0; i < 8; i++) {
        int rowg = m0 + r0t + 16 * i;
        rv[i] = rowg < NN;
        rbase[i] = (size_t)rowg * 256 + c4;
        aDst[i] = (uint32_t)((r0t + 16 * i) * (SA_STRIDE * 2) + c4 * 8);
    }

    const uint32_t aLd = smb +
        (uint32_t)((w * 16 + (lane & 7) + ((lane >> 3) & 1) * 8) * (SA_STRIDE * 2) +
                   (lane >> 4) * 16);
    const uint32_t bLd = smb +
        (uint32_t)((((lane >> 4) * 8) + (lane & 7)) * (SA_STRIDE * 2) +
                   ((lane >> 3) & 1) * 16);

    float acc[8][4];
#pragma unroll
    for (int j = 0; j < 8; j++)
#pragma unroll
        for (int q = 0; q < 4; q++) acc[j][q] = 0.f;

    float4 pf[8];
#pragma unroll
    for (int i = 0; i < 8; i++)
        pf[i] = rv[i] ? __ldg(xb + rbase[i]) : make_float4(0.f, 0.f, 0.f, 0.f);

    for (int kc = 0; kc < 16; kc++) {
        // ---- B global loads first ----
        uint2 bh[4], bl[4];
#pragma unroll
        for (int j = 0; j < 4; j++) {
            int lin = t + j * 256;
            int n = lin >> 4, q = lin & 15;
            size_t src = (size_t)n * DF + kc * 64 + q * 4;
            bh[j] = __ldg((const uint2*)(g_W1h + src));
            bl[j] = __ldg((const uint2*)(g_W1l + src));
        }
        // ---- convert prefetched A: f32 -> bf16 hi/lo ----
#pragma unroll
        for (int i = 0; i < 8; i++) {
            float4 v = pf[i];
            __nv_bfloat16 hx = __float2bfloat16(v.x), hy = __float2bfloat16(v.y);
            __nv_bfloat16 hz = __float2bfloat16(v.z), hw = __float2bfloat16(v.w);
            *(uint2*)(sm + SAH_OFF + aDst[i]) =
                make_uint2(bfbits(hx) | (bfbits(hy) << 16), bfbits(hz) | (bfbits(hw) << 16));
            __nv_bfloat16 lx = __float2bfloat16(v.x - __bfloat162float(hx));
            __nv_bfloat16 ly = __float2bfloat16(v.y - __bfloat162float(hy));
            __nv_bfloat16 lz = __float2bfloat16(v.z - __bfloat162float(hz));
            __nv_bfloat16 lw = __float2bfloat16(v.w - __bfloat162float(hw));
            *(uint2*)(sm + SAL_OFF + aDst[i]) =
                make_uint2(bfbits(lx) | (bfbits(ly) << 16), bfbits(lz) | (bfbits(lw) << 16));
        }
        // ---- store B ----
#pragma unroll
        for (int j = 0; j < 4; j++) {
            int lin = t + j * 256;
            int n = lin >> 4, q = lin & 15;
            uint32_t dst = (uint32_t)(n * (SA_STRIDE * 2) + q * 8);
            *(uint2*)(sm + SBH_OFF + dst) = bh[j];
            *(uint2*)(sm + SBL_OFF + dst) = bl[j];
        }
        __syncthreads();

        // ---- prefetch next A chunk ----
        if (kc < 15) {
#pragma unroll
            for (int i = 0; i < 8; i++)
                pf[i] = rv[i] ? __ldg(xb + rbase[i] + (kc + 1) * 16)
                              : make_float4(0.f, 0.f, 0.f, 0.f);
        }

        // ---- compute ----
#pragma unroll
        for (int ks = 0; ks < 4; ks++) {
            uint32_t ah[4], al[4];
            LDSM4(ah, aLd + SAH_OFF + ks * 32);
            LDSM4(al, aLd + SAL_OFF + ks * 32);
#pragma unroll
            for (int jp = 0; jp < 4; jp++) {
                uint32_t vh[4], vl[4];
                LDSM4(vh, bLd + SBH_OFF + jp * (16 * SA_STRIDE * 2) + ks * 32);
                LDSM4(vl, bLd + SBL_OFF + jp * (16 * SA_STRIDE * 2) + ks * 32);
                mma16816(acc[2 * jp],     ah, vh[0], vh[1]);
                mma16816(acc[2 * jp],     ah, vl[0], vl[1]);
                mma16816(acc[2 * jp],     al, vh[0], vh[1]);
                mma16816(acc[2 * jp + 1], ah, vh[2], vh[3]);
                mma16816(acc[2 * jp + 1], ah, vl[2], vl[3]);
                mma16816(acc[2 * jp + 1], al, vh[2], vh[3]);
            }
        }
        __syncthreads();
    }

    // ---- epilogue ----
    const int g = lane >> 2, tig = lane & 3;
    const int r0 = m0 + w * 16 + g;
    const int r1 = r0 + 8;
#pragma unroll
    for (int nt = 0; nt < 8; nt++) {
        int c = nt * 8 + tig * 2;
        if (r0 < NN) *(float2*)(g_H1 + (size_t)r0 * 64 + c) = make_float2(acc[nt][0], acc[nt][1]);
        if (r1 < NN) *(float2*)(g_H1 + (size_t)r1 * 64 + c) = make_float2(acc[nt][2], acc[nt][3]);
    }
}

// ---------------- gather1 + relu + bias + GEMM2 fused (warp per node) ----------------
// NN = 40000 = 5000 blocks x 8 warps exactly.
__global__ void __launch_bounds__(256) k_gather1(const float* __restrict__ b1,
                                                 const float* __restrict__ W2) {
    __shared__ float sW[HID * NC];   // 10240 B
    __shared__ float sO[8][HID];     // 2048 B
    for (int i = threadIdx.x; i < HID * NC; i += 256) sW[i] = __ldg(W2 + i);
    __syncthreads();

    const int w = threadIdx.x >> 5, lane = threadIdx.x & 31;
    const int n = blockIdx.x * 8 + w;

    float di = __ldg(g_dinv + n);
    float2 acc = __ldg((const float2*)(g_H1 + (size_t)n * 64) + lane);
    acc.x *= di * di; acc.y *= di * di;

    const int start = __ldg(g_rowptr + n);
    const int cnt   = __ldg(g_deg + n);
    const int2* ep = g_edge + start;
    int i = 0;
    for (; i + 8 <= cnt; i += 8) {
        int2 e[8];
#pragma unroll
        for (int u = 0; u < 8; u++) e[u] = __ldg(ep + i + u);
        float2 v[8];
#pragma unroll
        for (int u = 0; u < 8; u++)
            v[u] = __ldg((const float2*)(g_H1 + (size_t)e[u].x * 64) + lane);
#pragma unroll
        for (int u = 0; u < 8; u++) {
            float wt = __int_as_float(e[u].y);
            acc.x = fmaf(wt, v[u].x, acc.x);
            acc.y = fmaf(wt, v[u].y, acc.y);
        }
    }
    for (; i < cnt; i++) {
        int2 e = __ldg(ep + i);
        float2 v = __ldg((const float2*)(g_H1 + (size_t)e.x * 64) + lane);
        float wt = __int_as_float(e.y);
        acc.x = fmaf(wt, v.x, acc.x); acc.y = fmaf(wt, v.y, acc.y);
    }
    float2 b = __ldg((const float2*)b1 + lane);
    sO[w][lane * 2]     = fmaxf(acc.x + b.x, 0.f);
    sO[w][lane * 2 + 1] = fmaxf(acc.y + b.y, 0.f);
    __syncwarp();

    // fused GEMM2: lanes 0..19 compute 2 classes each
    if (lane < 20) {
        float h0 = 0.f, h1 = 0.f;
        const float* o = sO[w];
#pragma unroll
        for (int k = 0; k < HID; k++) {
            float ov = o[k];
            h0 = fmaf(ov, sW[k * NC + 2 * lane],     h0);
            h1 = fmaf(ov, sW[k * NC + 2 * lane + 1], h1);
        }
        *(float2*)(g_H2 + (size_t)n * NC + lane * 2) = make_float2(h0, h1);
    }
}

// ---------------- gather layer 2 + bias + log_softmax (warp per node, MLP 8) ----------------
__global__ void __launch_bounds__(256) k_gather2(const float* __restrict__ b2,
                                                 float* __restrict__ out) {
    const int w = threadIdx.x >> 5, lane = threadIdx.x & 31;
    const int n = blockIdx.x * 8 + w;
    if (n >= NN) return;
    const bool act = lane < 20;  // 20 lanes x float2 = 40 cols
    float di = __ldg(g_dinv + n);
    float2 acc = make_float2(0.f, 0.f);
    if (act) {
        acc = __ldg((const float2*)(g_H2 + (size_t)n * NC) + lane);
        acc.x *= di * di; acc.y *= di * di;
    }
    const int start = __ldg(g_rowptr + n);
    const int cnt   = __ldg(g_deg + n);
    const int2* ep = g_edge + start;
    int i = 0;
    for (; i + 8 <= cnt; i += 8) {
        int2 e[8];
#pragma unroll
        for (int u = 0; u < 8; u++) e[u] = __ldg(ep + i + u);
        if (act) {
            float2 v[8];
#pragma unroll
            for (int u = 0; u < 8; u++)
                v[u] = __ldg((const float2*)(g_H2 + (size_t)e[u].x * NC) + lane);
#pragma unroll
            for (int u = 0; u < 8; u++) {
                float wt = __int_as_float(e[u].y);
                acc.x = fmaf(wt, v[u].x, acc.x);
                acc.y = fmaf(wt, v[u].y, acc.y);
            }
        }
    }
    for (; i < cnt; i++) {
        int2 e = __ldg(ep + i);
        if (act) {
            float2 v = __ldg((const float2*)(g_H2 + (size_t)e.x * NC) + lane);
            float wt = __int_as_float(e.y);
            acc.x = fmaf(wt, v.x, acc.x); acc.y = fmaf(wt, v.y, acc.y);
        }
    }
    float2 z = make_float2(-CUDART_INF_F, -CUDART_INF_F);
    if (act) {
        float2 b = __ldg((const float2*)b2 + lane);
        z = make_float2(acc.x + b.x, acc.y + b.y);
    }
    float m = fmaxf(z.x, z.y);
#pragma unroll
    for (int off = 16; off; off >>= 1) m = fmaxf(m, __shfl_xor_sync(0xffffffffu, m, off));
    float s = act ? (__expf(z.x - m) + __expf(z.y - m)) : 0.f;
#pragma unroll
    for (int off = 16; off; off >>= 1) s += __shfl_xor_sync(0xffffffffu, s, off);
    float l = m + __logf(s);
    if (act)
        *(float2*)(out + (size_t)n * NC + lane * 2) = make_float2(z.x - l, z.y - l);
}

// ---------------- launch ----------------
extern "C" void kernel_launch(void* const* d_in, const int* in_sizes, int n_in,
                              void* d_out, int out_size) {
    const float* x  = (const float*)d_in[0];
    const int*   ei = (const int*)d_in[1];
    const float* W1 = (const float*)d_in[2];
    const float* b1 = (const float*)d_in[3];
    const float* W2 = (const float*)d_in[4];
    const float* b2 = (const float*)d_in[5];
    const int* row = ei;         // sources
    const int* col = ei + NE;    // targets
    float* out = (float*)d_out;

    static void* deg_ptr = nullptr;
    static cudaStream_t s2 = nullptr;
    static cudaEvent_t evFork = nullptr, evJoin = nullptr;
    if (!deg_ptr) {  // resolved on the (non-captured) correctness call
        cudaFuncSetAttribute(k_gemm1, cudaFuncAttributeMaxDynamicSharedMemorySize, SM_TOTAL);
        cudaGetSymbolAddress(&deg_ptr, g_deg);
        cudaStreamCreateWithFlags(&s2, cudaStreamNonBlocking);
        cudaEventCreateWithFlags(&evFork, cudaEventDisableTiming);
        cudaEventCreateWithFlags(&evJoin, cudaEventDisableTiming);
    }

    // fork: stream B does wsplit + gemm1 (independent of CSR chain)
    cudaEventRecord(evFork, 0);
    cudaStreamWaitEvent(s2, evFork, 0);
    k_wsplit<<<(DF * HID + 255) / 256, 256, 0, s2>>>(W1);
    k_gemm1<<<(NN + 127) / 128, 256, SM_TOTAL, s2>>>(x);
    cudaEventRecord(evJoin, s2);

    // default stream: CSR build chain
    cudaMemsetAsync(deg_ptr, 0, NN * sizeof(int));
    k_hist<<<(NE + 255) / 256, 256>>>(col);
    k_scanA<<<SCAN_NB, 256>>>();
    k_scanB<<<1, 256>>>();
    k_scanC<<<SCAN_NB, 256>>>();
    k_fill<<<(NE + 255) / 256, 256>>>(row, col);

    // join, then fused gather1+gemm2 and gather2
    cudaStreamWaitEvent(0, evJoin, 0);
    k_gather1<<<NN / 8, 256>>>(b1, W2);
    k_gather2<<<(NN + 7) / 8, 256>>>(b2, out);
}